// round 15
// baseline (speedup 1.0000x reference)
#include <cuda_runtime.h>
#include <cuda_fp16.h>
#include <math.h>
#include <stdint.h>

// Problem constants
#define NN    4096
#define INF   4096
#define HH    1024
#define PP    256
// TAU = 0.5 -> 1/TAU = 2.0 ;  ALPHA = 0.8

// ---------------------------------------------------------------------------
// Scratch (device globals; no allocation allowed)
// ---------------------------------------------------------------------------
__device__ __half g_hx [2 * NN * INF];     // fp16 x1,x2
__device__ __half g_hG [2 * NN * NN];      // fp16 G1,G2 (pre-scaled by 4096)
__device__ __half g_hw [13500416];         // fp16 transposed weights [N,K], packed
__device__ __half g_tTh[2 * NN * HH];      // fp16 T^T [1024,4096] (both views)
__device__ __half g_zh [2 * NN * 2 * HH];  // fp16 copy of z (both views)
__device__ __half g_p1h[2 * NN * HH];
__device__ __half g_p2h[2 * NN * 512];
__device__ __half g_p3h[2 * NN * 256];
__device__ __half g_p4h[2 * NN * 512];
__device__ __half g_n1h[NN * PP];
__device__ __half g_n2h[NN * PP];
__device__ float  g_n1[NN * PP];
__device__ float  g_n2[NN * PP];
__device__ float  g_R[4 * NN];             // R11, R22, B12, B21
__device__ float  g_dot[NN];
__device__ float  g_partR[3 * 32 * NN];    // 3 expsum passes of row partials
__device__ float  g_partC[32 * NN];

// offsets (halves) into g_hw  (transposed: [N,K])
#define OFF_W1A  0
#define OFF_W1B  4194304
#define OFF_W2A  5242880
#define OFF_W2B  9437184
#define OFF_FC1  10485760
#define OFF_FC11 12582912
#define OFF_FC12 13107200
#define OFF_FC2  13238272
#define OFF_FC3  13369344

// ---------------------------------------------------------------------------
// Helpers
// ---------------------------------------------------------------------------
__device__ __forceinline__ uint32_t h2u(__half2 h) {
    union { __half2 h; uint32_t u; } cvt;
    cvt.h = h;
    return cvt.u;
}

__device__ __forceinline__ void mma_fp16(float* d, const uint32_t* a, uint32_t b0, uint32_t b1) {
    asm volatile(
        "mma.sync.aligned.m16n8k16.row.col.f32.f16.f16.f32 "
        "{%0,%1,%2,%3}, {%4,%5,%6,%7}, {%8,%9}, {%0,%1,%2,%3};"
        : "+f"(d[0]), "+f"(d[1]), "+f"(d[2]), "+f"(d[3])
        : "r"(a[0]), "r"(a[1]), "r"(a[2]), "r"(a[3]), "r"(b0), "r"(b1));
}

__device__ __forceinline__ void ldsm4(uint32_t* r, uint32_t a) {
    asm volatile("ldmatrix.sync.aligned.m8n8.x4.shared.b16 {%0,%1,%2,%3}, [%4];"
                 : "=r"(r[0]), "=r"(r[1]), "=r"(r[2]), "=r"(r[3]) : "r"(a));
}

__device__ __forceinline__ void cp16(const __half* smem_dst, const __half* gmem_src) {
    uint32_t s = (uint32_t)__cvta_generic_to_shared(smem_dst);
    asm volatile("cp.async.cg.shared.global [%0], [%1], 16;" :: "r"(s), "l"(gmem_src));
}

// ---------------------------------------------------------------------------
// Batched fp32 -> fp16 conversion: z selects {x1, x2, G1, G2}.
// ---------------------------------------------------------------------------
__global__ void cvt_batch_kernel(const float4* __restrict__ x1, const float4* __restrict__ x2,
                                 const float4* __restrict__ G1, const float4* __restrict__ G2,
                                 uint2* __restrict__ hx, uint2* __restrict__ hG, int n4)
{
    int i = blockIdx.x * blockDim.x + threadIdx.x;
    if (i >= n4) return;
    const int z = blockIdx.z;
    const float4* src = (z == 0) ? x1 : (z == 1) ? x2 : (z == 2) ? G1 : G2;
    uint2* dst = (z < 2) ? (hx + (size_t)z * n4) : (hG + (size_t)(z - 2) * n4);
    float scale = (z < 2) ? 1.0f : 4096.0f;
    float4 v = src[i];
    __half2 lo = __floats2half2_rn(v.x * scale, v.y * scale);
    __half2 hi = __floats2half2_rn(v.z * scale, v.w * scale);
    dst[i] = make_uint2(h2u(lo), h2u(hi));
}

// ---------------------------------------------------------------------------
// Batched fp32 [rows,cols] -> fp16 transposed [cols,rows] for up to 8 matrices.
// ---------------------------------------------------------------------------
struct CvtTDesc { const float* src; __half* dst; int rows; int cols; int tileEnd; };
struct CvtTBatch { CvtTDesc d[8]; int count; };

__global__ void cvtT_batch_kernel(CvtTBatch b)
{
    __shared__ __half tile[32][33];
    int t = blockIdx.x;
    int di = 0;
    while (di < b.count - 1 && t >= b.d[di].tileEnd) di++;
    if (t >= b.d[di].tileEnd) return;
    int tileStart = (di == 0) ? 0 : b.d[di - 1].tileEnd;
    int local = t - tileStart;
    const CvtTDesc D = b.d[di];
    int tilesPerRowBand = D.cols / 32;
    int r0 = (local / tilesPerRowBand) * 32;
    int c0 = (local % tilesPerRowBand) * 32;

    int x = threadIdx.x, y = threadIdx.y;  // 32x8
#pragma unroll
    for (int i = 0; i < 32; i += 8)
        tile[y + i][x] = __float2half_rn(D.src[(size_t)(r0 + y + i) * D.cols + c0 + x]);
    __syncthreads();
#pragma unroll
    for (int i = 0; i < 32; i += 8)
        D.dst[(size_t)(c0 + y + i) * D.rows + r0 + x] = tile[x][y + i];
}

// ---------------------------------------------------------------------------
// FP16 tensor-core GEMM, dual-view (blockIdx.z): acc = A @ B^T (fp32 accum);
// out = act(acc*postScale + bias_col + bias_row).
// A[M,K] fp16 (lda), BT[N,K] fp16 (ldb).
// 128x128 CTA tile, 128 THREADS (4 warps of 64x64), 2 CTA/SM, ldmatrix,
// 3-stage cp.async pipeline, one barrier per k-tile.
// ACT: 0=none, 1=leaky_relu(0.25), 2=elu
// ---------------------------------------------------------------------------
struct GemmView {
    const __half* A;
    const __half* BT;
    const float*  bias;     // indexed by output column (N dim), or null
    const float*  biasRow;  // indexed by output row (M dim), or null
    float*        C32;
    __half*       C16;
};

#define SK 72                          // smem k-stride in halves (64 + 8)
#define TILE_HALVES (128 * SK)         // 18432 B
#define NSTAGE 3
#define HG_SMEM_BYTES (NSTAGE * 2 * TILE_HALVES * 2)   // 110592

__device__ __forceinline__ float apply_act(float v, int ACT) {
    if (ACT == 1) return (v > 0.f) ? v : 0.25f * v;
    if (ACT == 2) return (v > 0.f) ? v : expm1f(v);
    return v;
}

template <int ACT>
__global__ void __launch_bounds__(128, 2)
hgemm_kernel(GemmView v0, GemmView v1, int lda, int ldb,
             float postScale, int ldc, int K)
{
    const GemmView V = blockIdx.z ? v1 : v0;
    extern __shared__ __half smh[];
    const uint32_t sbase = (uint32_t)__cvta_generic_to_shared(smh);

    const int tid  = threadIdx.x;
    const int lane = tid & 31;
    const int w    = tid >> 5;             // 0..3
    const int wm   = w >> 1;               // 0..1  (64 rows)
    const int wn   = w & 1;                // 0..1  (64 cols)
    const int brow = blockIdx.y * 128;
    const int bcol = blockIdx.x * 128;

    float acc[4][8][4];
#pragma unroll
    for (int mi = 0; mi < 4; mi++)
#pragma unroll
        for (int ni = 0; ni < 8; ni++)
#pragma unroll
            for (int r = 0; r < 4; r++) acc[mi][ni][r] = 0.f;

    auto load_tile = [&](int s) {
        int k0 = s * 64;
        __half* As = smh + (s % NSTAGE) * 2 * TILE_HALVES;
        __half* Bs = As + TILE_HALVES;
#pragma unroll
        for (int i = 0; i < 8; i++) {
            int f = i * 128 + tid;          // 1024 chunks of 8 halves per matrix
            int r = f >> 3, c8 = (f & 7) * 8;
            cp16(As + r * SK + c8, V.A + (size_t)(brow + r) * lda + k0 + c8);
            cp16(Bs + r * SK + c8, V.BT + (size_t)(bcol + r) * ldb + k0 + c8);
        }
        asm volatile("cp.async.commit_group;");
    };

    const int nst = K >> 6;
    load_tile(0);
    load_tile(1);

    const int a_row = wm * 64 + (lane & 15);
    const int a_koff = (lane >> 4) * 8;
    const int b_row = wn * 64 + ((lane >> 4) * 8) + (lane & 7);
    const int b_koff = ((lane >> 3) & 1) * 8;

    for (int s = 0; s < nst; s++) {
        if (s + 1 < nst) asm volatile("cp.async.wait_group 1;");
        else             asm volatile("cp.async.wait_group 0;");
        __syncthreads();
        if (s + 2 < nst) load_tile(s + 2);

        const uint32_t aab = sbase + ((s % NSTAGE) * 2 * TILE_HALVES) * 2;
        const uint32_t bbb = aab + TILE_HALVES * 2;

#pragma unroll
        for (int ks = 0; ks < 4; ks++) {
            const int kb = ks * 16;
            uint32_t afr[4][4];
#pragma unroll
            for (int mi = 0; mi < 4; mi++)
                ldsm4(afr[mi], aab + (((a_row + mi * 16) * SK) + kb + a_koff) * 2);
            uint32_t bq[4][4];
#pragma unroll
            for (int p = 0; p < 4; p++)
                ldsm4(bq[p], bbb + (((b_row + p * 16) * SK) + kb + b_koff) * 2);
#pragma unroll
            for (int mi = 0; mi < 4; mi++)
#pragma unroll
                for (int ni = 0; ni < 8; ni++)
                    mma_fp16(acc[mi][ni], afr[mi],
                             bq[ni >> 1][(ni & 1) * 2], bq[ni >> 1][(ni & 1) * 2 + 1]);
        }
        // one barrier per k-tile: next iteration's leading barrier protects
        // buffer (s-1)%3 before load_tile(s+2) overwrites it.
    }

#pragma unroll
    for (int mi = 0; mi < 4; mi++) {
        int r0 = brow + wm * 64 + mi * 16 + (lane >> 2);
        float br0 = 0.f, br8 = 0.f;
        if (V.biasRow) { br0 = V.biasRow[r0]; br8 = V.biasRow[r0 + 8]; }
#pragma unroll
        for (int ni = 0; ni < 8; ni++) {
            int c = bcol + wn * 64 + ni * 8 + (lane & 3) * 2;
            float bx = 0.f, by = 0.f;
            if (V.bias) { float2 bv = *(const float2*)(V.bias + c); bx = bv.x; by = bv.y; }
            float v[4];
            v[0] = apply_act(fmaf(acc[mi][ni][0], postScale, bx + br0), ACT);
            v[1] = apply_act(fmaf(acc[mi][ni][1], postScale, by + br0), ACT);
            v[2] = apply_act(fmaf(acc[mi][ni][2], postScale, bx + br8), ACT);
            v[3] = apply_act(fmaf(acc[mi][ni][3], postScale, by + br8), ACT);
            if (V.C32) {
                *(float2*)(V.C32 + (size_t)r0 * ldc + c)       = make_float2(v[0], v[1]);
                *(float2*)(V.C32 + (size_t)(r0 + 8) * ldc + c) = make_float2(v[2], v[3]);
            }
            if (V.C16) {
                *(uint32_t*)(V.C16 + (size_t)r0 * ldc + c)       = h2u(__floats2half2_rn(v[0], v[1]));
                *(uint32_t*)(V.C16 + (size_t)(r0 + 8) * ldc + c) = h2u(__floats2half2_rn(v[2], v[3]));
            }
        }
    }
}

// ---------------------------------------------------------------------------
// Batched FP16 exp-similarity with symmetry exploitation (unchanged, 256 thr).
// ---------------------------------------------------------------------------
#define NTRI 528    // 32*33/2

__global__ void __launch_bounds__(256, 2)
expsum3_kernel(const __half* __restrict__ n1h, const __half* __restrict__ n2h,
               float* __restrict__ partR, float* __restrict__ partC,
               int Nr, int K)
{
    const int zz = blockIdx.z;
    int bi, bj;
    const __half *A, *B;
    float *pR, *pC = nullptr;
    if (zz < 2) {
        int t = blockIdx.x;
        if (t >= NTRI) return;
        int b = (int)((65.0f - sqrtf(4225.0f - 8.0f * (float)t)) * 0.5f);
        while ((b + 1) * 32 - ((b + 1) * b) / 2 <= t) b++;
        while (b * 32 - (b * (b - 1)) / 2 > t) b--;
        bi = b;
        bj = bi + (t - (bi * 32 - bi * (bi - 1) / 2));
        A = B = (zz == 0) ? n1h : n2h;
        pR = partR + (size_t)zz * 32 * Nr;
    } else {
        bi = blockIdx.x >> 5;
        bj = blockIdx.x & 31;
        A = n1h; B = n2h;
        pR = partR + (size_t)2 * 32 * Nr;
        pC = partC;
    }
    const int brow = bi * 128;
    const int bcol = bj * 128;

    extern __shared__ __half smh[];
    const uint32_t sbase = (uint32_t)__cvta_generic_to_shared(smh);
    __shared__ float rbuf[128][4];
    __shared__ float cbuf[128][2];

    const int tid  = threadIdx.x;
    const int lane = tid & 31;
    const int w    = tid >> 5;
    const int wm   = w >> 2;
    const int wn   = w & 3;

    float acc[4][4][4];
#pragma unroll
    for (int mi = 0; mi < 4; mi++)
#pragma unroll
        for (int ni = 0; ni < 4; ni++)
#pragma unroll
            for (int r = 0; r < 4; r++) acc[mi][ni][r] = 0.f;

    auto load_tile = [&](int s) {
        int k0 = s * 64;
        __half* As = smh + (s % NSTAGE) * 2 * TILE_HALVES;
        __half* Bs = As + TILE_HALVES;
#pragma unroll
        for (int i = 0; i < 4; i++) {
            int f = i * 256 + tid;
            int r = f >> 3, c8 = (f & 7) * 8;
            cp16(As + r * SK + c8, A + (size_t)(brow + r) * K + k0 + c8);
            cp16(Bs + r * SK + c8, B + (size_t)(bcol + r) * K + k0 + c8);
        }
        asm volatile("cp.async.commit_group;");
    };

    const int nst = K >> 6;
    load_tile(0);
    load_tile(1);

    const int a_row = wm * 64 + (lane & 15);
    const int a_koff = (lane >> 4) * 8;
    const int b_row = wn * 32 + ((lane >> 4) * 8) + (lane & 7);
    const int b_koff = ((lane >> 3) & 1) * 8;

    for (int s = 0; s < nst; s++) {
        if (s + 1 < nst) asm volatile("cp.async.wait_group 1;");
        else             asm volatile("cp.async.wait_group 0;");
        __syncthreads();
        if (s + 2 < nst) load_tile(s + 2);

        const uint32_t aab = sbase + ((s % NSTAGE) * 2 * TILE_HALVES) * 2;
        const uint32_t bbb = aab + TILE_HALVES * 2;

#pragma unroll
        for (int ks = 0; ks < 4; ks++) {
            const int kb = ks * 16;
            uint32_t afr[4][4];
#pragma unroll
            for (int mi = 0; mi < 4; mi++)
                ldsm4(afr[mi], aab + (((a_row + mi * 16) * SK) + kb + a_koff) * 2);
            uint32_t bq[2][4];
#pragma unroll
            for (int p = 0; p < 2; p++)
                ldsm4(bq[p], bbb + (((b_row + p * 16) * SK) + kb + b_koff) * 2);
#pragma unroll
            for (int mi = 0; mi < 4; mi++)
#pragma unroll
                for (int ni = 0; ni < 4; ni++)
                    mma_fp16(acc[mi][ni], afr[mi], bq[ni >> 1][(ni & 1) * 2], bq[ni >> 1][(ni & 1) * 2 + 1]);
        }
    }

    float rsum[4][2], csum[4][2];
#pragma unroll
    for (int i = 0; i < 4; i++) { rsum[i][0] = rsum[i][1] = 0.f; csum[i][0] = csum[i][1] = 0.f; }
#pragma unroll
    for (int mi = 0; mi < 4; mi++)
#pragma unroll
        for (int ni = 0; ni < 4; ni++) {
            float e0 = __expf(2.0f * acc[mi][ni][0]);
            float e1 = __expf(2.0f * acc[mi][ni][1]);
            float e2 = __expf(2.0f * acc[mi][ni][2]);
            float e3 = __expf(2.0f * acc[mi][ni][3]);
            rsum[mi][0] += e0 + e1;
            rsum[mi][1] += e2 + e3;
            csum[ni][0] += e0 + e2;
            csum[ni][1] += e1 + e3;
        }

#pragma unroll
    for (int mi = 0; mi < 4; mi++)
#pragma unroll
        for (int h = 0; h < 2; h++) {
            float s = rsum[mi][h];
            s += __shfl_down_sync(0xffffffffu, s, 2, 4);
            s += __shfl_down_sync(0xffffffffu, s, 1, 4);
            if ((lane & 3) == 0)
                rbuf[wm * 64 + mi * 16 + h * 8 + (lane >> 2)][wn] = s;
        }

#pragma unroll
    for (int ni = 0; ni < 4; ni++)
#pragma unroll
        for (int h = 0; h < 2; h++) {
            float s = csum[ni][h];
            s += __shfl_down_sync(0xffffffffu, s, 16);
            s += __shfl_down_sync(0xffffffffu, s, 8);
            s += __shfl_down_sync(0xffffffffu, s, 4);
            if (lane < 4)
                cbuf[wn * 32 + ni * 8 + lane * 2 + h][wm] = s;
        }

    __syncthreads();
    if (tid < 128) {
        float rs = rbuf[tid][0] + rbuf[tid][1] + rbuf[tid][2] + rbuf[tid][3];
        pR[(size_t)bj * Nr + brow + tid] = rs;
        float cs = cbuf[tid][0] + cbuf[tid][1];
        if (zz < 2) {
            if (bi != bj)
                pR[(size_t)bi * Nr + bcol + tid] = cs;
        } else {
            pC[(size_t)bi * Nr + bcol + tid] = cs;
        }
    }
}

// ---------------------------------------------------------------------------
// Small kernels
// ---------------------------------------------------------------------------
__global__ void reduce_all_kernel(const float* __restrict__ partR,
                                  const float* __restrict__ partC,
                                  float* __restrict__ R, int n)
{
    int i = blockIdx.x * blockDim.x + threadIdx.x;
    int which = blockIdx.y;
    if (i < n) {
        const float* src = (which < 3) ? (partR + (size_t)which * 32 * n) : partC;
        float s = 0.f;
        for (int b = 0; b < 32; b++) s += src[(size_t)b * n + i];
        R[(size_t)which * n + i] = s;
    }
}

__global__ void normalize2_kernel(float* __restrict__ h1, float* __restrict__ h2,
                                  __half* __restrict__ h1h, __half* __restrict__ h2h,
                                  int n, int p)
{
    float* h = blockIdx.y ? h2 : h1;
    __half* hh = blockIdx.y ? h2h : h1h;
    int row  = blockIdx.x * (blockDim.x >> 5) + (threadIdx.x >> 5);
    int lane = threadIdx.x & 31;
    if (row >= n) return;
    float s = 0.f;
    for (int c = lane; c < p; c += 32) { float v = h[(size_t)row * p + c]; s += v * v; }
#pragma unroll
    for (int o = 16; o; o >>= 1) s += __shfl_xor_sync(0xffffffffu, s, o);
    float inv = 1.f / fmaxf(sqrtf(s), 1e-12f);
    for (int c = lane; c < p; c += 32) {
        float v = h[(size_t)row * p + c] * inv;
        h[(size_t)row * p + c] = v;
        hh[(size_t)row * p + c] = __float2half_rn(v);
    }
}

__global__ void rowdot_kernel(const float* __restrict__ a, const float* __restrict__ b,
                              float* __restrict__ out, int n, int p)
{
    int row  = blockIdx.x * (blockDim.x >> 5) + (threadIdx.x >> 5);
    int lane = threadIdx.x & 31;
    if (row >= n) return;
    float s = 0.f;
    for (int c = lane; c < p; c += 32) s += a[(size_t)row * p + c] * b[(size_t)row * p + c];
#pragma unroll
    for (int o = 16; o; o >>= 1) s += __shfl_xor_sync(0xffffffffu, s, o);
    if (lane == 0) out[row] = s;
}

__global__ void loss_kernel(const float* __restrict__ R,   // [R11 R22 B12 B21] x n
                            const float* __restrict__ dot, float* __restrict__ out, int n)
{
    __shared__ float sh[256];
    const float E2 = expf(2.0f);
    const float* R11 = R;
    const float* R22 = R + n;
    const float* B12 = R + 2 * n;
    const float* B21 = R + 3 * n;
    float s = 0.f;
    for (int i = threadIdx.x; i < n; i += 256) {
        s += 0.8f * logf(R11[i] + B12[i] - E2)
           + 0.2f * logf(R22[i] + B21[i] - E2)
           - 2.0f * dot[i];
    }
    sh[threadIdx.x] = s;
    __syncthreads();
    for (int o = 128; o; o >>= 1) {
        if (threadIdx.x < o) sh[threadIdx.x] += sh[threadIdx.x + o];
        __syncthreads();
    }
    if (threadIdx.x == 0) out[0] = sh[0];
}

// ---------------------------------------------------------------------------
// Host orchestration
// ---------------------------------------------------------------------------
static void launch_hgemm(int act, GemmView v0, GemmView v1, int lda, int ldb,
                         float postScale, int ldc, int M, int N, int K)
{
    dim3 grid(N / 128, M / 128, 2), block(128);
    switch (act) {
        case 0:
            cudaFuncSetAttribute(hgemm_kernel<0>, cudaFuncAttributeMaxDynamicSharedMemorySize, HG_SMEM_BYTES);
            hgemm_kernel<0><<<grid, block, HG_SMEM_BYTES>>>(v0, v1, lda, ldb, postScale, ldc, K);
            break;
        case 1:
            cudaFuncSetAttribute(hgemm_kernel<1>, cudaFuncAttributeMaxDynamicSharedMemorySize, HG_SMEM_BYTES);
            hgemm_kernel<1><<<grid, block, HG_SMEM_BYTES>>>(v0, v1, lda, ldb, postScale, ldc, K);
            break;
        default:
            cudaFuncSetAttribute(hgemm_kernel<2>, cudaFuncAttributeMaxDynamicSharedMemorySize, HG_SMEM_BYTES);
            hgemm_kernel<2><<<grid, block, HG_SMEM_BYTES>>>(v0, v1, lda, ldb, postScale, ldc, K);
            break;
    }
}

extern "C" void kernel_launch(void* const* d_in, const int* in_sizes, int n_in,
                              void* d_out, int out_size)
{
    const float* x[2]   = { (const float*)d_in[0], (const float*)d_in[2] };
    const float* G[2]   = { (const float*)d_in[1], (const float*)d_in[3] };
    const float* Wa[2]  = { (const float*)d_in[4], (const float*)d_in[8] };
    const float* ba[2]  = { (const float*)d_in[5], (const float*)d_in[9] };
    const float* Wb[2]  = { (const float*)d_in[6], (const float*)d_in[10] };
    const float* bb[2]  = { (const float*)d_in[7], (const float*)d_in[11] };
    const float* fc1_w  = (const float*)d_in[12];
    const float* fc1_b  = (const float*)d_in[13];
    const float* fc11_w = (const float*)d_in[14];
    const float* fc11_b = (const float*)d_in[15];
    const float* fc12_w = (const float*)d_in[16];
    const float* fc12_b = (const float*)d_in[17];
    const float* fc2_w  = (const float*)d_in[18];
    const float* fc2_b  = (const float*)d_in[19];
    const float* fc3_w  = (const float*)d_in[20];
    const float* fc3_b  = (const float*)d_in[21];

    float* out = (float*)d_out;

    __half *hx, *hG, *hw, *tTh, *zh, *p1h, *p2h, *p3h, *p4h, *n1h, *n2h;
    float *n1, *n2, *R, *dot, *partR, *partC;
    cudaGetSymbolAddress((void**)&hx,  g_hx);
    cudaGetSymbolAddress((void**)&hG,  g_hG);
    cudaGetSymbolAddress((void**)&hw,  g_hw);
    cudaGetSymbolAddress((void**)&tTh, g_tTh);
    cudaGetSymbolAddress((void**)&zh,  g_zh);
    cudaGetSymbolAddress((void**)&p1h, g_p1h);
    cudaGetSymbolAddress((void**)&p2h, g_p2h);
    cudaGetSymbolAddress((void**)&p3h, g_p3h);
    cudaGetSymbolAddress((void**)&p4h, g_p4h);
    cudaGetSymbolAddress((void**)&n1h, g_n1h);
    cudaGetSymbolAddress((void**)&n2h, g_n2h);
    cudaGetSymbolAddress((void**)&n1,  g_n1);
    cudaGetSymbolAddress((void**)&n2,  g_n2);
    cudaGetSymbolAddress((void**)&R,   g_R);
    cudaGetSymbolAddress((void**)&dot, g_dot);
    cudaGetSymbolAddress((void**)&partR, g_partR);
    cudaGetSymbolAddress((void**)&partC, g_partC);

    const float INV = 1.0f / 4096.0f;
    const size_t ZV = (size_t)NN * 2 * HH;     // per-view z size
    const size_t TV = (size_t)HH * NN;         // per-view T^T size

    // --- batched prepass: one cvt launch + two cvtT launches ---
    {
        int n4 = NN * INF / 4;
        dim3 grid((n4 + 255) / 256, 1, 4);
        cvt_batch_kernel<<<grid, 256>>>((const float4*)x[0], (const float4*)x[1],
                                        (const float4*)G[0], (const float4*)G[1],
                                        (uint2*)hx, (uint2*)hG, n4);
    }
    {
        CvtTBatch b;
        int acc = 0;
        auto add = [&](int i, const float* s, __half* d, int r, int c) {
            acc += (r / 32) * (c / 32);
            b.d[i] = { s, d, r, c, acc };
        };
        add(0, Wa[0],  hw + OFF_W1A,  INF, HH);
        add(1, Wa[1],  hw + OFF_W2A,  INF, HH);
        add(2, Wb[0],  hw + OFF_W1B,  HH,  HH);
        add(3, Wb[1],  hw + OFF_W2B,  HH,  HH);
        add(4, fc1_w,  hw + OFF_FC1,  2 * HH, HH);
        add(5, fc11_w, hw + OFF_FC11, HH,  512);
        add(6, fc12_w, hw + OFF_FC12, 512, 256);
        add(7, fc2_w,  hw + OFF_FC2,  256, 512);
        b.count = 8;
        cvtT_batch_kernel<<<acc, dim3(32, 8)>>>(b);
        CvtTBatch b2;
        b2.d[0] = { fc3_w, hw + OFF_FC3, 512, 256, (512 / 32) * (256 / 32) };
        b2.count = 1;
        cvtT_batch_kernel<<<b2.d[0].tileEnd, dim3(32, 8)>>>(b2);
    }

    // T1^T = WaT @ x^T (+ row-bias ba): [HH, NN]
    launch_hgemm(0,
        { hw + OFF_W1A, hx,            nullptr, ba[0], nullptr, tTh },
        { hw + OFF_W2A, hx + NN * INF, nullptr, ba[1], nullptr, tTh + TV },
        INF, INF, 1.f, NN, HH, NN, INF);

    // H1 = leaky(G@T1): fp32 -> z slices of out, fp16 -> zh
    launch_hgemm(1,
        { hG,           tTh,      nullptr, nullptr, out,      zh },
        { hG + NN * NN, tTh + TV, nullptr, nullptr, out + ZV, zh + ZV },
        NN, NN, INV, 2 * HH, NN, HH, NN);
    // T2^T = WbT @ H1^T (+ row-bias bb): [HH, NN]
    launch_hgemm(0,
        { hw + OFF_W1B, zh,      nullptr, bb[0], nullptr, tTh },
        { hw + OFF_W2B, zh + ZV, nullptr, bb[1], nullptr, tTh + TV },
        HH, 2 * HH, 1.f, NN, HH, NN, HH);
    // H2 = leaky(G@T2)
    launch_hgemm(1,
        { hG,           tTh,      nullptr, nullptr, out + HH,      zh + HH },
        { hG + NN * NN, tTh + TV, nullptr, nullptr, out + ZV + HH, zh + ZV + HH },
        NN, NN, INV, 2 * HH, NN, HH, NN);

    // --- projection head (weights shared across views) ---
    launch_hgemm(2,
        { zh,      hw + OFF_FC1, fc1_b, nullptr, nullptr, p1h },
        { zh + ZV, hw + OFF_FC1, fc1_b, nullptr, nullptr, p1h + NN * HH },
        2 * HH, 2 * HH, 1.f, HH, NN, HH, 2 * HH);
    launch_hgemm(2,
        { p1h,           hw + OFF_FC11, fc11_b, nullptr, nullptr, p2h },
        { p1h + NN * HH, hw + OFF_FC11, fc11_b, nullptr, nullptr, p2h + NN * 512 },
        HH, HH, 1.f, 512, NN, 512, HH);
    launch_hgemm(2,
        { p2h,            hw + OFF_FC12, fc12_b, nullptr, nullptr, p3h },
        { p2h + NN * 512, hw + OFF_FC12, fc12_b, nullptr, nullptr, p3h + NN * 256 },
        512, 512, 1.f, 256, NN, 256, 512);
    launch_hgemm(2,
        { p3h,            hw + OFF_FC2, fc2_b, nullptr, nullptr, p4h },
        { p3h + NN * 256, hw + OFF_FC2, fc2_b, nullptr, nullptr, p4h + NN * 512 },
        256, 256, 1.f, 512, NN, 512, 256);
    launch_hgemm(0,
        { p4h,            hw + OFF_FC3, fc3_b, nullptr, n1, nullptr },
        { p4h + NN * 512, hw + OFF_FC3, fc3_b, nullptr, n2, nullptr },
        512, 512, 1.f, 256, NN, 256, 512);

    normalize2_kernel<<<dim3(NN / 8, 2), 256>>>(n1, n2, n1h, n2h, NN, PP);

    // --- batched exp-similarity: symmetric passes use triangular grids ---
    dim3 egrid(1024, 1, 3), eblock(256);
    cudaFuncSetAttribute(expsum3_kernel, cudaFuncAttributeMaxDynamicSharedMemorySize, HG_SMEM_BYTES);
    expsum3_kernel<<<egrid, eblock, HG_SMEM_BYTES>>>(n1h, n2h, partR, partC, NN, PP);
    reduce_all_kernel<<<dim3(NN / 256, 4), 256>>>(partR, partC, R, NN);

    rowdot_kernel<<<NN / 8, 256>>>(n1, n2, dot, NN, PP);

    loss_kernel<<<1, 256>>>(R, dot, out + (out_size - 1), NN);
}

// round 16
// speedup vs baseline: 1.0055x; 1.0055x over previous
#include <cuda_runtime.h>
#include <cuda_fp16.h>
#include <math.h>
#include <stdint.h>

// Problem constants
#define NN    4096
#define INF   4096
#define HH    1024
#define PP    256
// TAU = 0.5 -> 1/TAU = 2.0 ;  ALPHA = 0.8

// ---------------------------------------------------------------------------
// Scratch (device globals; no allocation allowed)
// ---------------------------------------------------------------------------
__device__ __half g_hx [2 * NN * INF];     // fp16 x1,x2
__device__ __half g_hG [2 * NN * NN];      // fp16 G1,G2 (pre-scaled by 4096)
__device__ __half g_hw [13500416];         // fp16 transposed weights [N,K], packed
__device__ __half g_tTh[2 * NN * HH];      // fp16 T^T [1024,4096] (both views)
__device__ __half g_zh [2 * NN * 2 * HH];  // fp16 copy of z (both views)
__device__ __half g_p1h[2 * NN * HH];
__device__ __half g_p2h[2 * NN * 512];
__device__ __half g_p3h[2 * NN * 256];
__device__ __half g_p4h[2 * NN * 512];
__device__ __half g_n1h[NN * PP];
__device__ __half g_n2h[NN * PP];
__device__ float  g_n1[NN * PP];
__device__ float  g_n2[NN * PP];
__device__ float  g_R[4 * NN];             // R11, R22, B12, B21
__device__ float  g_dot[NN];
__device__ float  g_partR[3 * 32 * NN];    // 3 expsum passes of row partials
__device__ float  g_partC[32 * NN];

// offsets (halves) into g_hw  (transposed: [N,K])
#define OFF_W1A  0
#define OFF_W1B  4194304
#define OFF_W2A  5242880
#define OFF_W2B  9437184
#define OFF_FC1  10485760
#define OFF_FC11 12582912
#define OFF_FC12 13107200
#define OFF_FC2  13238272
#define OFF_FC3  13369344

// ---------------------------------------------------------------------------
// Helpers
// ---------------------------------------------------------------------------
__device__ __forceinline__ uint32_t h2u(__half2 h) {
    union { __half2 h; uint32_t u; } cvt;
    cvt.h = h;
    return cvt.u;
}
__device__ __forceinline__ __half2 u2h(uint32_t u) {
    union { uint32_t u; __half2 h; } cvt;
    cvt.u = u;
    return cvt.h;
}

__device__ __forceinline__ void mma_fp16(float* d, const uint32_t* a, uint32_t b0, uint32_t b1) {
    asm volatile(
        "mma.sync.aligned.m16n8k16.row.col.f32.f16.f16.f32 "
        "{%0,%1,%2,%3}, {%4,%5,%6,%7}, {%8,%9}, {%0,%1,%2,%3};"
        : "+f"(d[0]), "+f"(d[1]), "+f"(d[2]), "+f"(d[3])
        : "r"(a[0]), "r"(a[1]), "r"(a[2]), "r"(a[3]), "r"(b0), "r"(b1));
}

// fp16-accumulate variant (d = 2 regs of half2); tests full-rate HMMA.F16
__device__ __forceinline__ void mma_fp16acc(uint32_t* d, const uint32_t* a, uint32_t b0, uint32_t b1) {
    asm volatile(
        "mma.sync.aligned.m16n8k16.row.col.f16.f16.f16.f16 "
        "{%0,%1}, {%2,%3,%4,%5}, {%6,%7}, {%0,%1};"
        : "+r"(d[0]), "+r"(d[1])
        : "r"(a[0]), "r"(a[1]), "r"(a[2]), "r"(a[3]), "r"(b0), "r"(b1));
}

__device__ __forceinline__ void ldsm4(uint32_t* r, uint32_t a) {
    asm volatile("ldmatrix.sync.aligned.m8n8.x4.shared.b16 {%0,%1,%2,%3}, [%4];"
                 : "=r"(r[0]), "=r"(r[1]), "=r"(r[2]), "=r"(r[3]) : "r"(a));
}

__device__ __forceinline__ void cp16(const __half* smem_dst, const __half* gmem_src) {
    uint32_t s = (uint32_t)__cvta_generic_to_shared(smem_dst);
    asm volatile("cp.async.cg.shared.global [%0], [%1], 16;" :: "r"(s), "l"(gmem_src));
}

// ---------------------------------------------------------------------------
// Batched fp32 -> fp16 conversion: z selects {x1, x2, G1, G2}.
// ---------------------------------------------------------------------------
__global__ void cvt_batch_kernel(const float4* __restrict__ x1, const float4* __restrict__ x2,
                                 const float4* __restrict__ G1, const float4* __restrict__ G2,
                                 uint2* __restrict__ hx, uint2* __restrict__ hG, int n4)
{
    int i = blockIdx.x * blockDim.x + threadIdx.x;
    if (i >= n4) return;
    const int z = blockIdx.z;
    const float4* src = (z == 0) ? x1 : (z == 1) ? x2 : (z == 2) ? G1 : G2;
    uint2* dst = (z < 2) ? (hx + (size_t)z * n4) : (hG + (size_t)(z - 2) * n4);
    float scale = (z < 2) ? 1.0f : 4096.0f;
    float4 v = src[i];
    __half2 lo = __floats2half2_rn(v.x * scale, v.y * scale);
    __half2 hi = __floats2half2_rn(v.z * scale, v.w * scale);
    dst[i] = make_uint2(h2u(lo), h2u(hi));
}

// ---------------------------------------------------------------------------
// Batched fp32 [rows,cols] -> fp16 transposed [cols,rows] for up to 8 matrices.
// ---------------------------------------------------------------------------
struct CvtTDesc { const float* src; __half* dst; int rows; int cols; int tileEnd; };
struct CvtTBatch { CvtTDesc d[8]; int count; };

__global__ void cvtT_batch_kernel(CvtTBatch b)
{
    __shared__ __half tile[32][33];
    int t = blockIdx.x;
    int di = 0;
    while (di < b.count - 1 && t >= b.d[di].tileEnd) di++;
    if (t >= b.d[di].tileEnd) return;
    int tileStart = (di == 0) ? 0 : b.d[di - 1].tileEnd;
    int local = t - tileStart;
    const CvtTDesc D = b.d[di];
    int tilesPerRowBand = D.cols / 32;
    int r0 = (local / tilesPerRowBand) * 32;
    int c0 = (local % tilesPerRowBand) * 32;

    int x = threadIdx.x, y = threadIdx.y;  // 32x8
#pragma unroll
    for (int i = 0; i < 32; i += 8)
        tile[y + i][x] = __float2half_rn(D.src[(size_t)(r0 + y + i) * D.cols + c0 + x]);
    __syncthreads();
#pragma unroll
    for (int i = 0; i < 32; i += 8)
        D.dst[(size_t)(c0 + y + i) * D.rows + r0 + x] = tile[x][y + i];
}

// ---------------------------------------------------------------------------
// FP16 tensor-core GEMM, dual-view (blockIdx.z): acc = A @ B^T (fp32 accum);
// out = act(acc*postScale + bias_col + bias_row).
// A[M,K] fp16 (lda), BT[N,K] fp16 (ldb).
// 128x128 CTA tile, 256 threads (8 warps of 64x32), 2 CTA/SM, ldmatrix,
// 3-stage cp.async pipeline, one barrier per k-tile.  [R13 config]
// ACT: 0=none, 1=leaky_relu(0.25), 2=elu
// ---------------------------------------------------------------------------
struct GemmView {
    const __half* A;
    const __half* BT;
    const float*  bias;     // indexed by output column (N dim), or null
    const float*  biasRow;  // indexed by output row (M dim), or null
    float*        C32;
    __half*       C16;
};

#define SK 72                          // smem k-stride in halves (64 + 8)
#define TILE_HALVES (128 * SK)         // 18432 B
#define NSTAGE 3
#define HG_SMEM_BYTES (NSTAGE * 2 * TILE_HALVES * 2)   // 110592

__device__ __forceinline__ float apply_act(float v, int ACT) {
    if (ACT == 1) return (v > 0.f) ? v : 0.25f * v;
    if (ACT == 2) return (v > 0.f) ? v : expm1f(v);
    return v;
}

template <int ACT>
__global__ void __launch_bounds__(256, 2)
hgemm_kernel(GemmView v0, GemmView v1, int lda, int ldb,
             float postScale, int ldc, int K)
{
    const GemmView V = blockIdx.z ? v1 : v0;
    extern __shared__ __half smh[];
    const uint32_t sbase = (uint32_t)__cvta_generic_to_shared(smh);

    const int tid  = threadIdx.x;
    const int lane = tid & 31;
    const int w    = tid >> 5;
    const int wm   = w >> 2;               // 0..1
    const int wn   = w & 3;                // 0..3
    const int brow = blockIdx.y * 128;
    const int bcol = blockIdx.x * 128;

    float acc[4][4][4];
#pragma unroll
    for (int mi = 0; mi < 4; mi++)
#pragma unroll
        for (int ni = 0; ni < 4; ni++)
#pragma unroll
            for (int r = 0; r < 4; r++) acc[mi][ni][r] = 0.f;

    auto load_tile = [&](int s) {
        int k0 = s * 64;
        __half* As = smh + (s % NSTAGE) * 2 * TILE_HALVES;
        __half* Bs = As + TILE_HALVES;
#pragma unroll
        for (int i = 0; i < 4; i++) {
            int f = i * 256 + tid;
            int r = f >> 3, c8 = (f & 7) * 8;
            cp16(As + r * SK + c8, V.A + (size_t)(brow + r) * lda + k0 + c8);
            cp16(Bs + r * SK + c8, V.BT + (size_t)(bcol + r) * ldb + k0 + c8);
        }
        asm volatile("cp.async.commit_group;");
    };

    const int nst = K >> 6;
    load_tile(0);
    load_tile(1);

    const int a_row = wm * 64 + (lane & 15);
    const int a_koff = (lane >> 4) * 8;
    const int b_row = wn * 32 + ((lane >> 4) * 8) + (lane & 7);
    const int b_koff = ((lane >> 3) & 1) * 8;

    for (int s = 0; s < nst; s++) {
        if (s + 1 < nst) asm volatile("cp.async.wait_group 1;");
        else             asm volatile("cp.async.wait_group 0;");
        __syncthreads();
        if (s + 2 < nst) load_tile(s + 2);

        const uint32_t aab = sbase + ((s % NSTAGE) * 2 * TILE_HALVES) * 2;
        const uint32_t bbb = aab + TILE_HALVES * 2;

#pragma unroll
        for (int ks = 0; ks < 4; ks++) {
            const int kb = ks * 16;
            uint32_t afr[4][4];
#pragma unroll
            for (int mi = 0; mi < 4; mi++)
                ldsm4(afr[mi], aab + (((a_row + mi * 16) * SK) + kb + a_koff) * 2);
            uint32_t bq[2][4];
#pragma unroll
            for (int p = 0; p < 2; p++)
                ldsm4(bq[p], bbb + (((b_row + p * 16) * SK) + kb + b_koff) * 2);
#pragma unroll
            for (int mi = 0; mi < 4; mi++)
#pragma unroll
                for (int ni = 0; ni < 4; ni++)
                    mma_fp16(acc[mi][ni], afr[mi], bq[ni >> 1][(ni & 1) * 2], bq[ni >> 1][(ni & 1) * 2 + 1]);
        }
        // one barrier per k-tile: next iteration's leading barrier protects
        // buffer (s-1)%3 before load_tile(s+2) overwrites it.
    }

#pragma unroll
    for (int mi = 0; mi < 4; mi++) {
        int r0 = brow + wm * 64 + mi * 16 + (lane >> 2);
        float br0 = 0.f, br8 = 0.f;
        if (V.biasRow) { br0 = V.biasRow[r0]; br8 = V.biasRow[r0 + 8]; }
#pragma unroll
        for (int ni = 0; ni < 4; ni++) {
            int c = bcol + wn * 32 + ni * 8 + (lane & 3) * 2;
            float bx = 0.f, by = 0.f;
            if (V.bias) { float2 bv = *(const float2*)(V.bias + c); bx = bv.x; by = bv.y; }
            float v[4];
            v[0] = apply_act(fmaf(acc[mi][ni][0], postScale, bx + br0), ACT);
            v[1] = apply_act(fmaf(acc[mi][ni][1], postScale, by + br0), ACT);
            v[2] = apply_act(fmaf(acc[mi][ni][2], postScale, bx + br8), ACT);
            v[3] = apply_act(fmaf(acc[mi][ni][3], postScale, by + br8), ACT);
            if (V.C32) {
                *(float2*)(V.C32 + (size_t)r0 * ldc + c)       = make_float2(v[0], v[1]);
                *(float2*)(V.C32 + (size_t)(r0 + 8) * ldc + c) = make_float2(v[2], v[3]);
            }
            if (V.C16) {
                *(uint32_t*)(V.C16 + (size_t)r0 * ldc + c)       = h2u(__floats2half2_rn(v[0], v[1]));
                *(uint32_t*)(V.C16 + (size_t)(r0 + 8) * ldc + c) = h2u(__floats2half2_rn(v[2], v[3]));
            }
        }
    }
}

// ---------------------------------------------------------------------------
// Batched FP16 exp-similarity, symmetry-exploiting, **fp16 accumulators**
// (|dot| <= 1 so fp16 chain over K=256 adds ~1e-3 abs on the dot; loss-only).
// ---------------------------------------------------------------------------
#define NTRI 528    // 32*33/2

__global__ void __launch_bounds__(256, 2)
expsum3_kernel(const __half* __restrict__ n1h, const __half* __restrict__ n2h,
               float* __restrict__ partR, float* __restrict__ partC,
               int Nr, int K)
{
    const int zz = blockIdx.z;
    int bi, bj;
    const __half *A, *B;
    float *pR, *pC = nullptr;
    if (zz < 2) {
        int t = blockIdx.x;
        if (t >= NTRI) return;
        int b = (int)((65.0f - sqrtf(4225.0f - 8.0f * (float)t)) * 0.5f);
        while ((b + 1) * 32 - ((b + 1) * b) / 2 <= t) b++;
        while (b * 32 - (b * (b - 1)) / 2 > t) b--;
        bi = b;
        bj = bi + (t - (bi * 32 - bi * (bi - 1) / 2));
        A = B = (zz == 0) ? n1h : n2h;
        pR = partR + (size_t)zz * 32 * Nr;
    } else {
        bi = blockIdx.x >> 5;
        bj = blockIdx.x & 31;
        A = n1h; B = n2h;
        pR = partR + (size_t)2 * 32 * Nr;
        pC = partC;
    }
    const int brow = bi * 128;
    const int bcol = bj * 128;

    extern __shared__ __half smh[];
    const uint32_t sbase = (uint32_t)__cvta_generic_to_shared(smh);
    __shared__ float rbuf[128][4];
    __shared__ float cbuf[128][2];

    const int tid  = threadIdx.x;
    const int lane = tid & 31;
    const int w    = tid >> 5;
    const int wm   = w >> 2;
    const int wn   = w & 3;

    uint32_t acc[4][4][2];   // fp16x2 accumulators
#pragma unroll
    for (int mi = 0; mi < 4; mi++)
#pragma unroll
        for (int ni = 0; ni < 4; ni++) { acc[mi][ni][0] = 0u; acc[mi][ni][1] = 0u; }

    auto load_tile = [&](int s) {
        int k0 = s * 64;
        __half* As = smh + (s % NSTAGE) * 2 * TILE_HALVES;
        __half* Bs = As + TILE_HALVES;
#pragma unroll
        for (int i = 0; i < 4; i++) {
            int f = i * 256 + tid;
            int r = f >> 3, c8 = (f & 7) * 8;
            cp16(As + r * SK + c8, A + (size_t)(brow + r) * K + k0 + c8);
            cp16(Bs + r * SK + c8, B + (size_t)(bcol + r) * K + k0 + c8);
        }
        asm volatile("cp.async.commit_group;");
    };

    const int nst = K >> 6;
    load_tile(0);
    load_tile(1);

    const int a_row = wm * 64 + (lane & 15);
    const int a_koff = (lane >> 4) * 8;
    const int b_row = wn * 32 + ((lane >> 4) * 8) + (lane & 7);
    const int b_koff = ((lane >> 3) & 1) * 8;

    for (int s = 0; s < nst; s++) {
        if (s + 1 < nst) asm volatile("cp.async.wait_group 1;");
        else             asm volatile("cp.async.wait_group 0;");
        __syncthreads();
        if (s + 2 < nst) load_tile(s + 2);

        const uint32_t aab = sbase + ((s % NSTAGE) * 2 * TILE_HALVES) * 2;
        const uint32_t bbb = aab + TILE_HALVES * 2;

#pragma unroll
        for (int ks = 0; ks < 4; ks++) {
            const int kb = ks * 16;
            uint32_t afr[4][4];
#pragma unroll
            for (int mi = 0; mi < 4; mi++)
                ldsm4(afr[mi], aab + (((a_row + mi * 16) * SK) + kb + a_koff) * 2);
            uint32_t bq[2][4];
#pragma unroll
            for (int p = 0; p < 2; p++)
                ldsm4(bq[p], bbb + (((b_row + p * 16) * SK) + kb + b_koff) * 2);
#pragma unroll
            for (int mi = 0; mi < 4; mi++)
#pragma unroll
                for (int ni = 0; ni < 4; ni++)
                    mma_fp16acc(acc[mi][ni], afr[mi], bq[ni >> 1][(ni & 1) * 2], bq[ni >> 1][(ni & 1) * 2 + 1]);
        }
    }

    float rsum[4][2], csum[4][2];
#pragma unroll
    for (int i = 0; i < 4; i++) { rsum[i][0] = rsum[i][1] = 0.f; csum[i][0] = csum[i][1] = 0.f; }
#pragma unroll
    for (int mi = 0; mi < 4; mi++)
#pragma unroll
        for (int ni = 0; ni < 4; ni++) {
            __half2 d0 = u2h(acc[mi][ni][0]);   // {c0, c1}
            __half2 d1 = u2h(acc[mi][ni][1]);   // {c2, c3}
            float e0 = __expf(2.0f * __low2float(d0));
            float e1 = __expf(2.0f * __high2float(d0));
            float e2 = __expf(2.0f * __low2float(d1));
            float e3 = __expf(2.0f * __high2float(d1));
            rsum[mi][0] += e0 + e1;
            rsum[mi][1] += e2 + e3;
            csum[ni][0] += e0 + e2;
            csum[ni][1] += e1 + e3;
        }

#pragma unroll
    for (int mi = 0; mi < 4; mi++)
#pragma unroll
        for (int h = 0; h < 2; h++) {
            float s = rsum[mi][h];
            s += __shfl_down_sync(0xffffffffu, s, 2, 4);
            s += __shfl_down_sync(0xffffffffu, s, 1, 4);
            if ((lane & 3) == 0)
                rbuf[wm * 64 + mi * 16 + h * 8 + (lane >> 2)][wn] = s;
        }

#pragma unroll
    for (int ni = 0; ni < 4; ni++)
#pragma unroll
        for (int h = 0; h < 2; h++) {
            float s = csum[ni][h];
            s += __shfl_down_sync(0xffffffffu, s, 16);
            s += __shfl_down_sync(0xffffffffu, s, 8);
            s += __shfl_down_sync(0xffffffffu, s, 4);
            if (lane < 4)
                cbuf[wn * 32 + ni * 8 + lane * 2 + h][wm] = s;
        }

    __syncthreads();
    if (tid < 128) {
        float rs = rbuf[tid][0] + rbuf[tid][1] + rbuf[tid][2] + rbuf[tid][3];
        pR[(size_t)bj * Nr + brow + tid] = rs;
        float cs = cbuf[tid][0] + cbuf[tid][1];
        if (zz < 2) {
            if (bi != bj)
                pR[(size_t)bi * Nr + bcol + tid] = cs;
        } else {
            pC[(size_t)bi * Nr + bcol + tid] = cs;
        }
    }
}

// ---------------------------------------------------------------------------
// Small kernels
// ---------------------------------------------------------------------------
__global__ void reduce_all_kernel(const float* __restrict__ partR,
                                  const float* __restrict__ partC,
                                  float* __restrict__ R, int n)
{
    int i = blockIdx.x * blockDim.x + threadIdx.x;
    int which = blockIdx.y;
    if (i < n) {
        const float* src = (which < 3) ? (partR + (size_t)which * 32 * n) : partC;
        float s = 0.f;
        for (int b = 0; b < 32; b++) s += src[(size_t)b * n + i];
        R[(size_t)which * n + i] = s;
    }
}

__global__ void normalize2_kernel(float* __restrict__ h1, float* __restrict__ h2,
                                  __half* __restrict__ h1h, __half* __restrict__ h2h,
                                  int n, int p)
{
    float* h = blockIdx.y ? h2 : h1;
    __half* hh = blockIdx.y ? h2h : h1h;
    int row  = blockIdx.x * (blockDim.x >> 5) + (threadIdx.x >> 5);
    int lane = threadIdx.x & 31;
    if (row >= n) return;
    float s = 0.f;
    for (int c = lane; c < p; c += 32) { float v = h[(size_t)row * p + c]; s += v * v; }
#pragma unroll
    for (int o = 16; o; o >>= 1) s += __shfl_xor_sync(0xffffffffu, s, o);
    float inv = 1.f / fmaxf(sqrtf(s), 1e-12f);
    for (int c = lane; c < p; c += 32) {
        float v = h[(size_t)row * p + c] * inv;
        h[(size_t)row * p + c] = v;
        hh[(size_t)row * p + c] = __float2half_rn(v);
    }
}

__global__ void rowdot_kernel(const float* __restrict__ a, const float* __restrict__ b,
                              float* __restrict__ out, int n, int p)
{
    int row  = blockIdx.x * (blockDim.x >> 5) + (threadIdx.x >> 5);
    int lane = threadIdx.x & 31;
    if (row >= n) return;
    float s = 0.f;
    for (int c = lane; c < p; c += 32) s += a[(size_t)row * p + c] * b[(size_t)row * p + c];
#pragma unroll
    for (int o = 16; o; o >>= 1) s += __shfl_xor_sync(0xffffffffu, s, o);
    if (lane == 0) out[row] = s;
}

__global__ void loss_kernel(const float* __restrict__ R,   // [R11 R22 B12 B21] x n
                            const float* __restrict__ dot, float* __restrict__ out, int n)
{
    __shared__ float sh[256];
    const float E2 = expf(2.0f);
    const float* R11 = R;
    const float* R22 = R + n;
    const float* B12 = R + 2 * n;
    const float* B21 = R + 3 * n;
    float s = 0.f;
    for (int i = threadIdx.x; i < n; i += 256) {
        s += 0.8f * logf(R11[i] + B12[i] - E2)
           + 0.2f * logf(R22[i] + B21[i] - E2)
           - 2.0f * dot[i];
    }
    sh[threadIdx.x] = s;
    __syncthreads();
    for (int o = 128; o; o >>= 1) {
        if (threadIdx.x < o) sh[threadIdx.x] += sh[threadIdx.x + o];
        __syncthreads();
    }
    if (threadIdx.x == 0) out[0] = sh[0];
}

// ---------------------------------------------------------------------------
// Host orchestration
// ---------------------------------------------------------------------------
static void launch_hgemm(int act, GemmView v0, GemmView v1, int lda, int ldb,
                         float postScale, int ldc, int M, int N, int K)
{
    dim3 grid(N / 128, M / 128, 2), block(256);
    switch (act) {
        case 0:
            cudaFuncSetAttribute(hgemm_kernel<0>, cudaFuncAttributeMaxDynamicSharedMemorySize, HG_SMEM_BYTES);
            hgemm_kernel<0><<<grid, block, HG_SMEM_BYTES>>>(v0, v1, lda, ldb, postScale, ldc, K);
            break;
        case 1:
            cudaFuncSetAttribute(hgemm_kernel<1>, cudaFuncAttributeMaxDynamicSharedMemorySize, HG_SMEM_BYTES);
            hgemm_kernel<1><<<grid, block, HG_SMEM_BYTES>>>(v0, v1, lda, ldb, postScale, ldc, K);
            break;
        default:
            cudaFuncSetAttribute(hgemm_kernel<2>, cudaFuncAttributeMaxDynamicSharedMemorySize, HG_SMEM_BYTES);
            hgemm_kernel<2><<<grid, block, HG_SMEM_BYTES>>>(v0, v1, lda, ldb, postScale, ldc, K);
            break;
    }
}

extern "C" void kernel_launch(void* const* d_in, const int* in_sizes, int n_in,
                              void* d_out, int out_size)
{
    const float* x[2]   = { (const float*)d_in[0], (const float*)d_in[2] };
    const float* G[2]   = { (const float*)d_in[1], (const float*)d_in[3] };
    const float* Wa[2]  = { (const float*)d_in[4], (const float*)d_in[8] };
    const float* ba[2]  = { (const float*)d_in[5], (const float*)d_in[9] };
    const float* Wb[2]  = { (const float*)d_in[6], (const float*)d_in[10] };
    const float* bb[2]  = { (const float*)d_in[7], (const float*)d_in[11] };
    const float* fc1_w  = (const float*)d_in[12];
    const float* fc1_b  = (const float*)d_in[13];
    const float* fc11_w = (const float*)d_in[14];
    const float* fc11_b = (const float*)d_in[15];
    const float* fc12_w = (const float*)d_in[16];
    const float* fc12_b = (const float*)d_in[17];
    const float* fc2_w  = (const float*)d_in[18];
    const float* fc2_b  = (const float*)d_in[19];
    const float* fc3_w  = (const float*)d_in[20];
    const float* fc3_b  = (const float*)d_in[21];

    float* out = (float*)d_out;

    __half *hx, *hG, *hw, *tTh, *zh, *p1h, *p2h, *p3h, *p4h, *n1h, *n2h;
    float *n1, *n2, *R, *dot, *partR, *partC;
    cudaGetSymbolAddress((void**)&hx,  g_hx);
    cudaGetSymbolAddress((void**)&hG,  g_hG);
    cudaGetSymbolAddress((void**)&hw,  g_hw);
    cudaGetSymbolAddress((void**)&tTh, g_tTh);
    cudaGetSymbolAddress((void**)&zh,  g_zh);
    cudaGetSymbolAddress((void**)&p1h, g_p1h);
    cudaGetSymbolAddress((void**)&p2h, g_p2h);
    cudaGetSymbolAddress((void**)&p3h, g_p3h);
    cudaGetSymbolAddress((void**)&p4h, g_p4h);
    cudaGetSymbolAddress((void**)&n1h, g_n1h);
    cudaGetSymbolAddress((void**)&n2h, g_n2h);
    cudaGetSymbolAddress((void**)&n1,  g_n1);
    cudaGetSymbolAddress((void**)&n2,  g_n2);
    cudaGetSymbolAddress((void**)&R,   g_R);
    cudaGetSymbolAddress((void**)&dot, g_dot);
    cudaGetSymbolAddress((void**)&partR, g_partR);
    cudaGetSymbolAddress((void**)&partC, g_partC);

    const float INV = 1.0f / 4096.0f;
    const size_t ZV = (size_t)NN * 2 * HH;     // per-view z size
    const size_t TV = (size_t)HH * NN;         // per-view T^T size

    // --- batched prepass: one cvt launch + two cvtT launches ---
    {
        int n4 = NN * INF / 4;
        dim3 grid((n4 + 255) / 256, 1, 4);
        cvt_batch_kernel<<<grid, 256>>>((const float4*)x[0], (const float4*)x[1],
                                        (const float4*)G[0], (const float4*)G[1],
                                        (uint2*)hx, (uint2*)hG, n4);
    }
    {
        CvtTBatch b;
        int acc = 0;
        auto add = [&](int i, const float* s, __half* d, int r, int c) {
            acc += (r / 32) * (c / 32);
            b.d[i] = { s, d, r, c, acc };
        };
        add(0, Wa[0],  hw + OFF_W1A,  INF, HH);
        add(1, Wa[1],  hw + OFF_W2A,  INF, HH);
        add(2, Wb[0],  hw + OFF_W1B,  HH,  HH);
        add(3, Wb[1],  hw + OFF_W2B,  HH,  HH);
        add(4, fc1_w,  hw + OFF_FC1,  2 * HH, HH);
        add(5, fc11_w, hw + OFF_FC11, HH,  512);
        add(6, fc12_w, hw + OFF_FC12, 512, 256);
        add(7, fc2_w,  hw + OFF_FC2,  256, 512);
        b.count = 8;
        cvtT_batch_kernel<<<acc, dim3(32, 8)>>>(b);
        CvtTBatch b2;
        b2.d[0] = { fc3_w, hw + OFF_FC3, 512, 256, (512 / 32) * (256 / 32) };
        b2.count = 1;
        cvtT_batch_kernel<<<b2.d[0].tileEnd, dim3(32, 8)>>>(b2);
    }

    // T1^T = WaT @ x^T (+ row-bias ba): [HH, NN]
    launch_hgemm(0,
        { hw + OFF_W1A, hx,            nullptr, ba[0], nullptr, tTh },
        { hw + OFF_W2A, hx + NN * INF, nullptr, ba[1], nullptr, tTh + TV },
        INF, INF, 1.f, NN, HH, NN, INF);

    // H1 = leaky(G@T1): fp32 -> z slices of out, fp16 -> zh
    launch_hgemm(1,
        { hG,           tTh,      nullptr, nullptr, out,      zh },
        { hG + NN * NN, tTh + TV, nullptr, nullptr, out + ZV, zh + ZV },
        NN, NN, INV, 2 * HH, NN, HH, NN);
    // T2^T = WbT @ H1^T (+ row-bias bb): [HH, NN]
    launch_hgemm(0,
        { hw + OFF_W1B, zh,      nullptr, bb[0], nullptr, tTh },
        { hw + OFF_W2B, zh + ZV, nullptr, bb[1], nullptr, tTh + TV },
        HH, 2 * HH, 1.f, NN, HH, NN, HH);
    // H2 = leaky(G@T2)
    launch_hgemm(1,
        { hG,           tTh,      nullptr, nullptr, out + HH,      zh + HH },
        { hG + NN * NN, tTh + TV, nullptr, nullptr, out + ZV + HH, zh + ZV + HH },
        NN, NN, INV, 2 * HH, NN, HH, NN);

    // --- projection head (weights shared across views) ---
    launch_hgemm(2,
        { zh,      hw + OFF_FC1, fc1_b, nullptr, nullptr, p1h },
        { zh + ZV, hw + OFF_FC1, fc1_b, nullptr, nullptr, p1h + NN * HH },
        2 * HH, 2 * HH, 1.f, HH, NN, HH, 2 * HH);
    launch_hgemm(2,
        { p1h,           hw + OFF_FC11, fc11_b, nullptr, nullptr, p2h },
        { p1h + NN * HH, hw + OFF_FC11, fc11_b, nullptr, nullptr, p2h + NN * 512 },
        HH, HH, 1.f, 512, NN, 512, HH);
    launch_hgemm(2,
        { p2h,            hw + OFF_FC12, fc12_b, nullptr, nullptr, p3h },
        { p2h + NN * 512, hw + OFF_FC12, fc12_b, nullptr, nullptr, p3h + NN * 256 },
        512, 512, 1.f, 256, NN, 256, 512);
    launch_hgemm(2,
        { p3h,            hw + OFF_FC2, fc2_b, nullptr, nullptr, p4h },
        { p3h + NN * 256, hw + OFF_FC2, fc2_b, nullptr, nullptr, p4h + NN * 512 },
        256, 256, 1.f, 512, NN, 512, 256);
    launch_hgemm(0,
        { p4h,            hw + OFF_FC3, fc3_b, nullptr, n1, nullptr },
        { p4h + NN * 512, hw + OFF_FC3, fc3_b, nullptr, n2, nullptr },
        512, 512, 1.f, 256, NN, 256, 512);

    normalize2_kernel<<<dim3(NN / 8, 2), 256>>>(n1, n2, n1h, n2h, NN, PP);

    // --- batched exp-similarity: symmetric passes use triangular grids ---
    dim3 egrid(1024, 1, 3), eblock(256);
    cudaFuncSetAttribute(expsum3_kernel, cudaFuncAttributeMaxDynamicSharedMemorySize, HG_SMEM_BYTES);
    expsum3_kernel<<<egrid, eblock, HG_SMEM_BYTES>>>(n1h, n2h, partR, partC, NN, PP);
    reduce_all_kernel<<<dim3(NN / 256, 4), 256>>>(partR, partC, R, NN);

    rowdot_kernel<<<NN / 8, 256>>>(n1, n2, dot, NN, PP);

    loss_kernel<<<1, 256>>>(R, dot, out + (out_size - 1), NN);
}